// round 15
// baseline (speedup 1.0000x reference)
#include <cuda_runtime.h>
#include <cuda_fp16.h>
#include <math.h>

#define BB 2
#define NN 2048
#define DD 1024
#define HH 16
#define HD 64
#define INNER (HH*HD)
#define NTOK (BB*NN)
#define EPS 1e-5f
#define SCQ 0.1803368801111204f   // 0.125 * log2(e)

// ------------------- scratch -------------------
static __device__ __align__(256) __half  g_xnh[NTOK*DD];
static __device__ __align__(256) __half  g_qh[BB*HH*NN*HD];   // rope-applied, pre-scaled by SCQ
static __device__ __align__(256) __half  g_kh[BB*HH*NN*HD];   // rope-applied
static __device__ __align__(256) __half  g_vh[BB*HH*NN*HD];
static __device__ __align__(256) __half  g_attnh[NTOK*INNER];
static __device__ __align__(256) __half  g_wqh[DD*3*INNER];
static __device__ __align__(256) __half  g_woh[INNER*DD];
static __device__ __align__(256) unsigned g_maskbits[BB*NN*(NN/32)];
static __device__ float g_invf[32];

// ------------------- asm helpers -------------------
__device__ __forceinline__ unsigned sptr(const void* p) {
    return (unsigned)__cvta_generic_to_shared(p);
}
__device__ __forceinline__ void cpa16(unsigned s, const void* g) {
    asm volatile("cp.async.cg.shared.global [%0], [%1], 16;\n" :: "r"(s), "l"(g));
}
#define CP_COMMIT asm volatile("cp.async.commit_group;\n" ::: "memory")
#define CP_WAIT2  asm volatile("cp.async.wait_group 2;\n" ::: "memory")
#define CP_WAIT1  asm volatile("cp.async.wait_group 1;\n" ::: "memory")
#define CP_WAIT0  asm volatile("cp.async.wait_group 0;\n" ::: "memory")

__device__ __forceinline__ void ldsm4(unsigned& r0, unsigned& r1, unsigned& r2, unsigned& r3, unsigned a) {
    asm volatile("ldmatrix.sync.aligned.m8n8.x4.shared.b16 {%0,%1,%2,%3}, [%4];"
        : "=r"(r0), "=r"(r1), "=r"(r2), "=r"(r3) : "r"(a));
}
__device__ __forceinline__ void ldsm4t(unsigned& r0, unsigned& r1, unsigned& r2, unsigned& r3, unsigned a) {
    asm volatile("ldmatrix.sync.aligned.m8n8.x4.trans.shared.b16 {%0,%1,%2,%3}, [%4];"
        : "=r"(r0), "=r"(r1), "=r"(r2), "=r"(r3) : "r"(a));
}
__device__ __forceinline__ void mma16(float* d, const unsigned* a, unsigned b0, unsigned b1) {
    asm volatile("mma.sync.aligned.m16n8k16.row.col.f32.f16.f16.f32 "
        "{%0,%1,%2,%3}, {%4,%5,%6,%7}, {%8,%9}, {%0,%1,%2,%3};"
        : "+f"(d[0]), "+f"(d[1]), "+f"(d[2]), "+f"(d[3])
        : "r"(a[0]), "r"(a[1]), "r"(a[2]), "r"(a[3]), "r"(b0), "r"(b1));
}
__device__ __forceinline__ unsigned h2pack(float lo, float hi) {
    __half2 h = __floats2half2_rn(lo, hi);
    return *(unsigned*)&h;
}
__device__ __forceinline__ unsigned cvt2h(float hi, float lo) {
    unsigned u; asm("cvt.rn.f16x2.f32 %0, %1, %2;" : "=r"(u) : "f"(hi), "f"(lo)); return u;
}
__device__ __forceinline__ unsigned ex2h2(unsigned x) {
    unsigned y; asm("ex2.approx.f16x2 %0, %1;" : "=r"(y) : "r"(x)); return y;
}

// ------------------- fused setup: weight cvt x2 | layernorm | mask pack | rope table ---
__global__ __launch_bounds__(256) void setup_kernel(const float* __restrict__ x,
                                                    const int* __restrict__ mask,
                                                    const float* __restrict__ gamma,
                                                    const float* __restrict__ beta,
                                                    const float* __restrict__ w_qkv,
                                                    const float* __restrict__ w_out) {
    int bid = blockIdx.x;
    int tid = threadIdx.x;
    if (bid < 2048) {
        const float* src = (bid < 1536) ? w_qkv : w_out;
        __half* dst      = (bid < 1536) ? g_wqh : g_woh;
        int base = (bid < 1536) ? bid : (bid - 1536);
        int i = (base * 256 + tid) * 8;
        float4 v0 = *(const float4*)(src + i);
        float4 v1 = *(const float4*)(src + i + 4);
        uint4 u;
        u.x = h2pack(v0.x, v0.y); u.y = h2pack(v0.z, v0.w);
        u.z = h2pack(v1.x, v1.y); u.w = h2pack(v1.z, v1.w);
        *(uint4*)(dst + i) = u;
    } else if (bid < 6144) {
        int t = bid - 2048;
        const float4* xv = (const float4*)(x + (size_t)t * DD);
        float4 v = xv[tid];
        float s  = v.x + v.y + v.z + v.w;
        float s2 = v.x*v.x + v.y*v.y + v.z*v.z + v.w*v.w;
        #pragma unroll
        for (int off = 16; off; off >>= 1) {
            s  += __shfl_xor_sync(0xffffffffu, s,  off);
            s2 += __shfl_xor_sync(0xffffffffu, s2, off);
        }
        __shared__ float ws[8], ws2[8];
        __shared__ float sh_mean, sh_inv;
        int lane = tid & 31, wid = tid >> 5;
        if (!lane) { ws[wid] = s; ws2[wid] = s2; }
        __syncthreads();
        if (tid == 0) {
            float a = 0.f, c = 0.f;
            #pragma unroll
            for (int i = 0; i < 8; i++) { a += ws[i]; c += ws2[i]; }
            float mean = a * (1.f/(float)DD);
            float var  = c * (1.f/(float)DD) - mean*mean;
            sh_mean = mean;
            sh_inv  = rsqrtf(var + EPS);
        }
        __syncthreads();
        float mean = sh_mean, inv = sh_inv;
        float4 g  = ((const float4*)gamma)[tid];
        float4 be = ((const float4*)beta)[tid];
        uint2 u;
        u.x = h2pack((v.x - mean) * inv * g.x + be.x, (v.y - mean) * inv * g.y + be.y);
        u.y = h2pack((v.z - mean) * inv * g.z + be.z, (v.w - mean) * inv * g.w + be.w);
        *(uint2*)(g_xnh + (size_t)t * DD + tid*4) = u;
    } else if (bid < 7168) {
        int w = (bid - 6144) * 256 + tid;
        const int4* mp = (const int4*)(mask + (size_t)w * 32);
        unsigned bits = 0;
        #pragma unroll
        for (int q = 0; q < 8; q++) {
            int4 m4 = mp[q];
            if (m4.x > 0) bits |= 1u << (q*4 + 0);
            if (m4.y > 0) bits |= 1u << (q*4 + 1);
            if (m4.z > 0) bits |= 1u << (q*4 + 2);
            if (m4.w > 0) bits |= 1u << (q*4 + 3);
        }
        g_maskbits[w] = bits;
    } else {
        if (tid < 32) g_invf[tid] = (float)pow(10000.0, -(double)tid / 32.0);
    }
}

// ------------------- fp16 GEMM: 128x128 tile, K-slab 64, 3-stage, SINGLE sync/slab ---
// mode 0: g_xnh @ g_wqh  -> fused RoPE -> g_qh/g_kh (half) + g_vh
// mode 1: g_attnh @ g_woh + bias -> out (fp32)
#define GA (128*72)        // A stage: 128 rows x 64 k (stride 72)
#define GB (64*136)        // B stage: 64 k x 128 n (stride 136)
#define GEMM_SMEM ((3*GA + 3*GB) * 2)   // 107520 B

__global__ __launch_bounds__(256, 2) void gemm_h(int Ncols, int mode,
                                                 const float* __restrict__ bias,
                                                 float* __restrict__ out) {
    const __half* A  = mode ? g_attnh : g_xnh;
    const __half* Bm = mode ? g_woh   : g_wqh;
    extern __shared__ __align__(16) __half gsm[];
    __half* As = gsm;
    __half* Bs = gsm + 3*GA;
    int tid = threadIdx.x, warp = tid >> 5, lane = tid & 31;
    int r = lane >> 2, cq = lane & 3;
    int wm = warp & 3, wn = warp >> 2;
    int m0 = blockIdx.y * 128, n0 = blockIdx.x * 128;

    float acc[2][8][4];
    #pragma unroll
    for (int t = 0; t < 2; t++)
        #pragma unroll
        for (int j = 0; j < 8; j++)
            #pragma unroll
            for (int u = 0; u < 4; u++) acc[t][j][u] = 0.f;

    auto loadst = [&](int kb, int s) {
        int k0 = kb * 64;
        __half* as = As + s*GA;
        __half* bs = Bs + s*GB;
        #pragma unroll
        for (int i = 0; i < 4; i++) {
            int c = tid + i*256;
            int row = c >> 3, k8 = (c & 7) * 8;
            cpa16(sptr(&as[row*72 + k8]), A + (size_t)(m0+row)*1024 + k0 + k8);
        }
        #pragma unroll
        for (int i = 0; i < 4; i++) {
            int c = tid + i*256;
            int k = c >> 4, n8 = (c & 15) * 8;
            cpa16(sptr(&bs[k*136 + n8]), Bm + (size_t)(k0+k)*Ncols + n0 + n8);
        }
    };

    loadst(0, 0); CP_COMMIT;
    loadst(1, 1); CP_COMMIT;
    for (int kb = 0; kb < 16; kb++) {
        CP_WAIT1;                 // slab kb's copies complete
        __syncthreads();          // ALSO orders prior compute-reads before new writes
        if (kb + 2 < 16) loadst(kb + 2, (kb + 2) % 3);
        CP_COMMIT;
        int s = kb % 3;
        __half* as = As + s*GA;
        __half* bs = Bs + s*GB;
        #pragma unroll
        for (int ks = 0; ks < 4; ks++) {
            unsigned a[2][4];
            #pragma unroll
            for (int t = 0; t < 2; t++) {
                unsigned ad = sptr(&as[(wm*32 + t*16 + (lane&7) + ((lane>>3)&1)*8)*72
                                       + ks*16 + ((lane>>4)&1)*8]);
                ldsm4(a[t][0], a[t][1], a[t][2], a[t][3], ad);
            }
            #pragma unroll
            for (int g = 0; g < 4; g++) {
                unsigned b0, b1, b2, b3;
                unsigned bd = sptr(&bs[(ks*16 + (lane&7) + ((lane>>3)&1)*8)*136
                                       + wn*64 + g*16 + ((lane>>4)&1)*8]);
                ldsm4t(b0, b1, b2, b3, bd);
                mma16(acc[0][2*g],   a[0], b0, b1);
                mma16(acc[1][2*g],   a[1], b0, b1);
                mma16(acc[0][2*g+1], a[0], b2, b3);
                mma16(acc[1][2*g+1], a[1], b2, b3);
            }
        }
        // no trailing sync: next iteration's top barrier provides the ordering
    }

    if (mode == 1) {
        #pragma unroll
        for (int t = 0; t < 2; t++) {
            int row_l = m0 + wm*32 + t*16 + r;
            int row_h = row_l + 8;
            #pragma unroll
            for (int j = 0; j < 8; j++) {
                int col0 = n0 + wn*64 + j*8 + cq*2;
                float2 bv = *(const float2*)&bias[col0];
                *(float2*)&out[(size_t)row_l*1024 + col0] =
                    make_float2(acc[t][j][0] + bv.x, acc[t][j][1] + bv.y);
                *(float2*)&out[(size_t)row_h*1024 + col0] =
                    make_float2(acc[t][j][2] + bv.x, acc[t][j][3] + bv.y);
            }
        }
        return;
    }

    int which = n0 >> 10;   // 0=q 1=k 2=v
    if (which == 2) {
        #pragma unroll
        for (int t = 0; t < 2; t++) {
            #pragma unroll
            for (int j = 0; j < 8; j++) {
                int col0 = n0 + wn*64 + j*8 + cq*2;
                #pragma unroll
                for (int u = 0; u < 4; u++) {
                    int mrow = m0 + wm*32 + t*16 + r + (u >> 1)*8;
                    int c = col0 + (u & 1);
                    int inner = c & 1023;
                    int h = inner >> 6, hd = inner & 63;
                    int b = mrow >> 11, n = mrow & 2047;
                    g_vh[(((size_t)(b*HH + h)) * NN + n) * HD + hd] =
                        __float2half_rn(acc[t][j][u]);
                }
            }
        }
    } else {
        __half* dst = which ? g_kh : g_qh;
        float sc = which ? 1.0f : SCQ;
        int head = ((n0 & 1023) + wn*64) >> 6;
        float inv0[4], inv1[4];
        #pragma unroll
        for (int j = 0; j < 4; j++) {
            inv0[j] = g_invf[j*8 + cq*2];
            inv1[j] = g_invf[j*8 + cq*2 + 1];
        }
        #pragma unroll
        for (int t = 0; t < 2; t++) {
            #pragma unroll
            for (int u = 0; u < 2; u++) {
                int mrow = m0 + wm*32 + t*16 + r + u*8;
                int n = mrow & 2047, bq = mrow >> 11;
                __half* base = dst + (((size_t)(bq*HH + head)) * NN + n) * HD;
                float fn = (float)n;
                #pragma unroll
                for (int j = 0; j < 4; j++) {
                    int i0 = j*8 + cq*2;
                    float a0 = acc[t][j][2*u],   a1 = acc[t][j][2*u+1];
                    float b0 = acc[t][j+4][2*u], b1 = acc[t][j+4][2*u+1];
                    float s0, c0, s1, c1;
                    sincosf(fn * inv0[j], &s0, &c0);
                    sincosf(fn * inv1[j], &s1, &c1);
                    *(__half2*)(base + i0) =
                        __floats2half2_rn((a0*c0 - b0*s0)*sc, (a1*c1 - b1*s1)*sc);
                    *(__half2*)(base + i0 + 32) =
                        __floats2half2_rn((b0*c0 + a0*s0)*sc, (b1*c1 + a1*s1)*sc);
                }
            }
        }
    }
}

// ------------------- fp16 flash attention: split K/V groups, V-wait deferred past S ---
#define QS 72
#define KVST (128*QS)
#define ATTN_SMEM ((4*KVST) * 2)   // 73728 B -> 2 CTAs/SM
#define ONESH2 0x3C003C00u

__global__ __launch_bounds__(256, 2) void attn_h() {
    extern __shared__ __align__(16) __half sm[];
    __half* Ks = sm;                // 2 x 128 x 72
    __half* Vs = sm + 2*KVST;       // 2 x 128 x 72

    int tid = threadIdx.x, warp = tid >> 5, lane = tid & 31;
    int r = lane >> 2, cq = lane & 3;
    int bid = blockIdx.x;
    int qt = bid & 15, bh = bid >> 4;
    int b = bh >> 4, head = bh & 15;
    int qrow0 = qt * 128;
    int wq = warp * 16;

    auto loadK = [&](int kt2, int s) {
        const __half* Kg = g_kh + ((size_t)bh * NN + kt2*128) * HD;
        #pragma unroll
        for (int i = 0; i < 4; i++) {
            int c = tid + i*256;
            int row = c >> 3, c8 = (c & 7) * 8;
            cpa16(sptr(&Ks[s*KVST + row*QS + c8]), Kg + row*HD + c8);
        }
    };
    auto loadV = [&](int kt2, int s) {
        const __half* Vg = g_vh + ((size_t)bh * NN + kt2*128) * HD;
        #pragma unroll
        for (int i = 0; i < 4; i++) {
            int c = tid + i*256;
            int row = c >> 3, c8 = (c & 7) * 8;
            cpa16(sptr(&Vs[s*KVST + row*QS + c8]), Vg + row*HD + c8);
        }
    };
    loadK(0, 0); CP_COMMIT;
    loadV(0, 0); CP_COMMIT;

    unsigned qa[4][4];
    {
        const __half* Qg = g_qh + ((size_t)bh * NN + qrow0 + wq + r) * HD + cq*2;
        #pragma unroll
        for (int ks = 0; ks < 4; ks++) {
            qa[ks][0] = *(const unsigned*)(Qg + ks*16);
            qa[ks][1] = *(const unsigned*)(Qg + 8*HD + ks*16);
            qa[ks][2] = *(const unsigned*)(Qg + ks*16 + 8);
            qa[ks][3] = *(const unsigned*)(Qg + 8*HD + ks*16 + 8);
        }
    }

    float O[8][4];
    #pragma unroll
    for (int j = 0; j < 8; j++)
        #pragma unroll
        for (int u = 0; u < 4; u++) O[j][u] = 0.f;
    float lf[4] = {0.f, 0.f, 0.f, 0.f};   // row sums via ones-mma

    const unsigned* mrow0 = g_maskbits + ((size_t)b * NN + qrow0 + wq + r) * (NN/32);
    const unsigned* mrow1 = mrow0 + 8 * (NN/32);

    for (int kt2 = 0; kt2 < NN/128; kt2++) {
        bool more = (kt2 + 1 < NN/128);
        CP_WAIT1;                 // K(kt2) complete (V(kt2) may still be in flight)
        __syncthreads();          // all warps done reading the stage about to be rewritten
        if (more) { loadK(kt2 + 1, (kt2 + 1) & 1); CP_COMMIT;
                    loadV(kt2 + 1, (kt2 + 1) & 1); CP_COMMIT; }
        int st = (kt2 & 1) * KVST;

        // ---- S = Q K^T for both 64-wide subtiles (V not needed yet) ----
        float S[2][8][4];
        #pragma unroll
        for (int hf = 0; hf < 2; hf++)
            #pragma unroll
            for (int j = 0; j < 8; j++)
                #pragma unroll
                for (int u = 0; u < 4; u++) S[hf][j][u] = 0.f;
        #pragma unroll
        for (int hf = 0; hf < 2; hf++) {
            int sb = st + hf * 64 * QS;
            #pragma unroll
            for (int ks = 0; ks < 4; ks++) {
                #pragma unroll
                for (int g = 0; g < 4; g++) {
                    unsigned b0, b1, b2, b3;
                    unsigned kd = sptr(&Ks[sb + ((2*g + ((lane>>4)&1))*8 + (lane&7))*QS
                                           + ks*16 + ((lane>>3)&1)*8]);
                    ldsm4(b0, b1, b2, b3, kd);
                    mma16(S[hf][2*g],   qa[ks], b0, b1);
                    mma16(S[hf][2*g+1], qa[ks], b2, b3);
                }
            }
        }

        if (more) { CP_WAIT2; }   // V(kt2) complete (leaves K/V of kt2+1 pending)
        else      { CP_WAIT0; }

        // ---- softmax + PV ----
        #pragma unroll
        for (int hf = 0; hf < 2; hf++) {
            int sb = st + hf * 64 * QS;
            int kt = kt2*2 + hf;
            unsigned mw00 = mrow0[kt*2], mw01 = mrow0[kt*2+1];
            unsigned mw10 = mrow1[kt*2], mw11 = mrow1[kt*2+1];

            #pragma unroll
            for (int ks = 0; ks < 4; ks++) {
                unsigned w0 = (ks < 2) ? mw00 : mw01;   // row_l
                unsigned w1 = (ks < 2) ? mw10 : mw11;   // row_h
                int bA = ((2*ks) & 3)*8 + cq*2;
                int bB = bA + 8;
                float s00 = ((w0 >> bA)     & 1u) ? S[hf][2*ks][0]   : -1e30f;
                float s01 = ((w0 >> (bA+1)) & 1u) ? S[hf][2*ks][1]   : -1e30f;
                float s02 = ((w1 >> bA)     & 1u) ? S[hf][2*ks][2]   : -1e30f;
                float s03 = ((w1 >> (bA+1)) & 1u) ? S[hf][2*ks][3]   : -1e30f;
                float s10 = ((w0 >> bB)     & 1u) ? S[hf][2*ks+1][0] : -1e30f;
                float s11 = ((w0 >> (bB+1)) & 1u) ? S[hf][2*ks+1][1] : -1e30f;
                float s12 = ((w1 >> bB)     & 1u) ? S[hf][2*ks+1][2] : -1e30f;
                float s13 = ((w1 >> (bB+1)) & 1u) ? S[hf][2*ks+1][3] : -1e30f;
                unsigned pk[4];
                pk[0] = ex2h2(cvt2h(s01, s00));
                pk[1] = ex2h2(cvt2h(s03, s02));
                pk[2] = ex2h2(cvt2h(s11, s10));
                pk[3] = ex2h2(cvt2h(s13, s12));
                mma16(lf, pk, ONESH2, ONESH2);   // row sums on tensor pipe
                #pragma unroll
                for (int g = 0; g < 4; g++) {
                    unsigned b0, b1, b2, b3;
                    unsigned vd = sptr(&Vs[sb + (ks*16 + (lane&7) + ((lane>>3)&1)*8)*QS
                                           + (2*g + ((lane>>4)&1))*8]);
                    ldsm4t(b0, b1, b2, b3, vd);
                    mma16(O[2*g],   pk, b0, b1);
                    mma16(O[2*g+1], pk, b2, b3);
                }
            }
        }
    }

    float i0 = (lf[0] > 0.f) ? (1.f / lf[0]) : 0.f;
    float i1 = (lf[2] > 0.f) ? (1.f / lf[2]) : 0.f;
    __half* o0 = g_attnh + ((size_t)b * NN + qrow0 + wq + r) * INNER + head * HD;
    __half* o1 = o0 + 8 * INNER;
    #pragma unroll
    for (int j = 0; j < 8; j++) {
        int col = j*8 + cq*2;
        *(__half2*)&o0[col] = __floats2half2_rn(O[j][0]*i0, O[j][1]*i0);
        *(__half2*)&o1[col] = __floats2half2_rn(O[j][2]*i1, O[j][3]*i1);
    }
}

// ------------------- launch -------------------
extern "C" void kernel_launch(void* const* d_in, const int* in_sizes, int n_in,
                              void* d_out, int out_size) {
    const float* x      = (const float*)d_in[0];
    const int*   mask   = (const int*)  d_in[1];
    const float* gamma  = (const float*)d_in[2];
    const float* beta   = (const float*)d_in[3];
    const float* w_qkv  = (const float*)d_in[4];
    const float* w_out  = (const float*)d_in[5];
    const float* b_out  = (const float*)d_in[6];
    float* out = (float*)d_out;

    static int attr_set = 0;
    if (!attr_set) {
        cudaFuncSetAttribute(attn_h, cudaFuncAttributeMaxDynamicSharedMemorySize, ATTN_SMEM);
        cudaFuncSetAttribute(gemm_h, cudaFuncAttributeMaxDynamicSharedMemorySize, GEMM_SMEM);
        attr_set = 1;
    }

    setup_kernel<<<7169, 256>>>(x, mask, gamma, beta, w_qkv, w_out);
    gemm_h<<<dim3(3*INNER/128, NTOK/128), 256, GEMM_SMEM>>>(3*INNER, 0, nullptr, nullptr);
    attn_h<<<BB*HH*(NN/128), 256, ATTN_SMEM>>>();
    gemm_h<<<dim3(DD/128, NTOK/128), 256, GEMM_SMEM>>>(DD, 1, b_out, out);
}

// round 16
// speedup vs baseline: 1.0455x; 1.0455x over previous
#include <cuda_runtime.h>
#include <cuda_fp16.h>
#include <math.h>

#define BB 2
#define NN 2048
#define DD 1024
#define HH 16
#define HD 64
#define INNER (HH*HD)
#define NTOK (BB*NN)
#define EPS 1e-5f
#define SCQ 0.1803368801111204f   // 0.125 * log2(e)

// ------------------- scratch -------------------
static __device__ __align__(256) __half  g_xnh[NTOK*DD];
static __device__ __align__(256) __half  g_qh[BB*HH*NN*HD];   // rope-applied, pre-scaled by SCQ
static __device__ __align__(256) __half  g_kh[BB*HH*NN*HD];   // rope-applied
static __device__ __align__(256) __half  g_vh[BB*HH*NN*HD];
static __device__ __align__(256) __half  g_attnh[NTOK*INNER];
static __device__ __align__(256) __half  g_wqh[DD*3*INNER];
static __device__ __align__(256) __half  g_woh[INNER*DD];
static __device__ __align__(256) unsigned g_maskbits[BB*NN*(NN/32)];
static __device__ float g_invf[32];

// ------------------- asm helpers -------------------
__device__ __forceinline__ unsigned sptr(const void* p) {
    return (unsigned)__cvta_generic_to_shared(p);
}
__device__ __forceinline__ void cpa16(unsigned s, const void* g) {
    asm volatile("cp.async.cg.shared.global [%0], [%1], 16;\n" :: "r"(s), "l"(g));
}
#define CP_COMMIT asm volatile("cp.async.commit_group;\n" ::: "memory")
#define CP_WAIT1  asm volatile("cp.async.wait_group 1;\n" ::: "memory")
#define CP_WAIT0  asm volatile("cp.async.wait_group 0;\n" ::: "memory")

__device__ __forceinline__ void ldsm4(unsigned& r0, unsigned& r1, unsigned& r2, unsigned& r3, unsigned a) {
    asm volatile("ldmatrix.sync.aligned.m8n8.x4.shared.b16 {%0,%1,%2,%3}, [%4];"
        : "=r"(r0), "=r"(r1), "=r"(r2), "=r"(r3) : "r"(a));
}
__device__ __forceinline__ void ldsm4t(unsigned& r0, unsigned& r1, unsigned& r2, unsigned& r3, unsigned a) {
    asm volatile("ldmatrix.sync.aligned.m8n8.x4.trans.shared.b16 {%0,%1,%2,%3}, [%4];"
        : "=r"(r0), "=r"(r1), "=r"(r2), "=r"(r3) : "r"(a));
}
__device__ __forceinline__ void mma16(float* d, const unsigned* a, unsigned b0, unsigned b1) {
    asm volatile("mma.sync.aligned.m16n8k16.row.col.f32.f16.f16.f32 "
        "{%0,%1,%2,%3}, {%4,%5,%6,%7}, {%8,%9}, {%0,%1,%2,%3};"
        : "+f"(d[0]), "+f"(d[1]), "+f"(d[2]), "+f"(d[3])
        : "r"(a[0]), "r"(a[1]), "r"(a[2]), "r"(a[3]), "r"(b0), "r"(b1));
}
__device__ __forceinline__ unsigned h2pack(float lo, float hi) {
    __half2 h = __floats2half2_rn(lo, hi);
    return *(unsigned*)&h;
}
__device__ __forceinline__ unsigned cvt2h(float hi, float lo) {
    unsigned u; asm("cvt.rn.f16x2.f32 %0, %1, %2;" : "=r"(u) : "f"(hi), "f"(lo)); return u;
}
__device__ __forceinline__ unsigned ex2h2(unsigned x) {
    unsigned y; asm("ex2.approx.f16x2 %0, %1;" : "=r"(y) : "r"(x)); return y;
}

// ------------------- fused setup: weight cvt x2 | layernorm | mask pack | rope table ---
__global__ __launch_bounds__(256) void setup_kernel(const float* __restrict__ x,
                                                    const int* __restrict__ mask,
                                                    const float* __restrict__ gamma,
                                                    const float* __restrict__ beta,
                                                    const float* __restrict__ w_qkv,
                                                    const float* __restrict__ w_out) {
    int bid = blockIdx.x;
    int tid = threadIdx.x;
    if (bid < 2048) {
        const float* src = (bid < 1536) ? w_qkv : w_out;
        __half* dst      = (bid < 1536) ? g_wqh : g_woh;
        int base = (bid < 1536) ? bid : (bid - 1536);
        int i = (base * 256 + tid) * 8;
        float4 v0 = *(const float4*)(src + i);
        float4 v1 = *(const float4*)(src + i + 4);
        uint4 u;
        u.x = h2pack(v0.x, v0.y); u.y = h2pack(v0.z, v0.w);
        u.z = h2pack(v1.x, v1.y); u.w = h2pack(v1.z, v1.w);
        *(uint4*)(dst + i) = u;
    } else if (bid < 6144) {
        int t = bid - 2048;
        const float4* xv = (const float4*)(x + (size_t)t * DD);
        float4 v = xv[tid];
        float s  = v.x + v.y + v.z + v.w;
        float s2 = v.x*v.x + v.y*v.y + v.z*v.z + v.w*v.w;
        #pragma unroll
        for (int off = 16; off; off >>= 1) {
            s  += __shfl_xor_sync(0xffffffffu, s,  off);
            s2 += __shfl_xor_sync(0xffffffffu, s2, off);
        }
        __shared__ float ws[8], ws2[8];
        __shared__ float sh_mean, sh_inv;
        int lane = tid & 31, wid = tid >> 5;
        if (!lane) { ws[wid] = s; ws2[wid] = s2; }
        __syncthreads();
        if (tid == 0) {
            float a = 0.f, c = 0.f;
            #pragma unroll
            for (int i = 0; i < 8; i++) { a += ws[i]; c += ws2[i]; }
            float mean = a * (1.f/(float)DD);
            float var  = c * (1.f/(float)DD) - mean*mean;
            sh_mean = mean;
            sh_inv  = rsqrtf(var + EPS);
        }
        __syncthreads();
        float mean = sh_mean, inv = sh_inv;
        float4 g  = ((const float4*)gamma)[tid];
        float4 be = ((const float4*)beta)[tid];
        uint2 u;
        u.x = h2pack((v.x - mean) * inv * g.x + be.x, (v.y - mean) * inv * g.y + be.y);
        u.y = h2pack((v.z - mean) * inv * g.z + be.z, (v.w - mean) * inv * g.w + be.w);
        *(uint2*)(g_xnh + (size_t)t * DD + tid*4) = u;
    } else if (bid < 7168) {
        int w = (bid - 6144) * 256 + tid;
        const int4* mp = (const int4*)(mask + (size_t)w * 32);
        unsigned bits = 0;
        #pragma unroll
        for (int q = 0; q < 8; q++) {
            int4 m4 = mp[q];
            if (m4.x > 0) bits |= 1u << (q*4 + 0);
            if (m4.y > 0) bits |= 1u << (q*4 + 1);
            if (m4.z > 0) bits |= 1u << (q*4 + 2);
            if (m4.w > 0) bits |= 1u << (q*4 + 3);
        }
        g_maskbits[w] = bits;
    } else {
        if (tid < 32) g_invf[tid] = (float)pow(10000.0, -(double)tid / 32.0);
    }
}

// ------------------- fp16 GEMM: 128x128 tile, K-slab 64, 3-stage, SINGLE sync/slab ---
// mode 0: g_xnh @ g_wqh  -> fused RoPE -> g_qh/g_kh (half) + g_vh
// mode 1: g_attnh @ g_woh + bias -> out (fp32)
#define GA (128*72)        // A stage: 128 rows x 64 k (stride 72)
#define GB (64*136)        // B stage: 64 k x 128 n (stride 136)
#define GEMM_SMEM ((3*GA + 3*GB) * 2)   // 107520 B

__global__ __launch_bounds__(256, 2) void gemm_h(int Ncols, int mode,
                                                 const float* __restrict__ bias,
                                                 float* __restrict__ out) {
    const __half* A  = mode ? g_attnh : g_xnh;
    const __half* Bm = mode ? g_woh   : g_wqh;
    extern __shared__ __align__(16) __half gsm[];
    __half* As = gsm;
    __half* Bs = gsm + 3*GA;
    int tid = threadIdx.x, warp = tid >> 5, lane = tid & 31;
    int r = lane >> 2, cq = lane & 3;
    int wm = warp & 3, wn = warp >> 2;
    int m0 = blockIdx.y * 128, n0 = blockIdx.x * 128;

    float acc[2][8][4];
    #pragma unroll
    for (int t = 0; t < 2; t++)
        #pragma unroll
        for (int j = 0; j < 8; j++)
            #pragma unroll
            for (int u = 0; u < 4; u++) acc[t][j][u] = 0.f;

    auto loadst = [&](int kb, int s) {
        int k0 = kb * 64;
        __half* as = As + s*GA;
        __half* bs = Bs + s*GB;
        #pragma unroll
        for (int i = 0; i < 4; i++) {
            int c = tid + i*256;
            int row = c >> 3, k8 = (c & 7) * 8;
            cpa16(sptr(&as[row*72 + k8]), A + (size_t)(m0+row)*1024 + k0 + k8);
        }
        #pragma unroll
        for (int i = 0; i < 4; i++) {
            int c = tid + i*256;
            int k = c >> 4, n8 = (c & 15) * 8;
            cpa16(sptr(&bs[k*136 + n8]), Bm + (size_t)(k0+k)*Ncols + n0 + n8);
        }
    };

    loadst(0, 0); CP_COMMIT;
    loadst(1, 1); CP_COMMIT;
    for (int kb = 0; kb < 16; kb++) {
        CP_WAIT1;                 // slab kb's copies complete
        __syncthreads();          // also orders prior compute-reads before new writes
        if (kb + 2 < 16) loadst(kb + 2, (kb + 2) % 3);
        CP_COMMIT;
        int s = kb % 3;
        __half* as = As + s*GA;
        __half* bs = Bs + s*GB;
        #pragma unroll
        for (int ks = 0; ks < 4; ks++) {
            unsigned a[2][4];
            #pragma unroll
            for (int t = 0; t < 2; t++) {
                unsigned ad = sptr(&as[(wm*32 + t*16 + (lane&7) + ((lane>>3)&1)*8)*72
                                       + ks*16 + ((lane>>4)&1)*8]);
                ldsm4(a[t][0], a[t][1], a[t][2], a[t][3], ad);
            }
            #pragma unroll
            for (int g = 0; g < 4; g++) {
                unsigned b0, b1, b2, b3;
                unsigned bd = sptr(&bs[(ks*16 + (lane&7) + ((lane>>3)&1)*8)*136
                                       + wn*64 + g*16 + ((lane>>4)&1)*8]);
                ldsm4t(b0, b1, b2, b3, bd);
                mma16(acc[0][2*g],   a[0], b0, b1);
                mma16(acc[1][2*g],   a[1], b0, b1);
                mma16(acc[0][2*g+1], a[0], b2, b3);
                mma16(acc[1][2*g+1], a[1], b2, b3);
            }
        }
        // no trailing sync: next iteration's top barrier provides the ordering
    }

    if (mode == 1) {
        #pragma unroll
        for (int t = 0; t < 2; t++) {
            int row_l = m0 + wm*32 + t*16 + r;
            int row_h = row_l + 8;
            #pragma unroll
            for (int j = 0; j < 8; j++) {
                int col0 = n0 + wn*64 + j*8 + cq*2;
                float2 bv = *(const float2*)&bias[col0];
                *(float2*)&out[(size_t)row_l*1024 + col0] =
                    make_float2(acc[t][j][0] + bv.x, acc[t][j][1] + bv.y);
                *(float2*)&out[(size_t)row_h*1024 + col0] =
                    make_float2(acc[t][j][2] + bv.x, acc[t][j][3] + bv.y);
            }
        }
        return;
    }

    int which = n0 >> 10;   // 0=q 1=k 2=v
    if (which == 2) {
        #pragma unroll
        for (int t = 0; t < 2; t++) {
            #pragma unroll
            for (int j = 0; j < 8; j++) {
                int col0 = n0 + wn*64 + j*8 + cq*2;
                #pragma unroll
                for (int u = 0; u < 4; u++) {
                    int mrow = m0 + wm*32 + t*16 + r + (u >> 1)*8;
                    int c = col0 + (u & 1);
                    int inner = c & 1023;
                    int h = inner >> 6, hd = inner & 63;
                    int b = mrow >> 11, n = mrow & 2047;
                    g_vh[(((size_t)(b*HH + h)) * NN + n) * HD + hd] =
                        __float2half_rn(acc[t][j][u]);
                }
            }
        }
    } else {
        __half* dst = which ? g_kh : g_qh;
        float sc = which ? 1.0f : SCQ;
        int head = ((n0 & 1023) + wn*64) >> 6;
        float inv0[4], inv1[4];
        #pragma unroll
        for (int j = 0; j < 4; j++) {
            inv0[j] = g_invf[j*8 + cq*2];
            inv1[j] = g_invf[j*8 + cq*2 + 1];
        }
        #pragma unroll
        for (int t = 0; t < 2; t++) {
            #pragma unroll
            for (int u = 0; u < 2; u++) {
                int mrow = m0 + wm*32 + t*16 + r + u*8;
                int n = mrow & 2047, bq = mrow >> 11;
                __half* base = dst + (((size_t)(bq*HH + head)) * NN + n) * HD;
                float fn = (float)n;
                #pragma unroll
                for (int j = 0; j < 4; j++) {
                    int i0 = j*8 + cq*2;
                    float a0 = acc[t][j][2*u],   a1 = acc[t][j][2*u+1];
                    float b0 = acc[t][j+4][2*u], b1 = acc[t][j+4][2*u+1];
                    float s0, c0, s1, c1;
                    sincosf(fn * inv0[j], &s0, &c0);
                    sincosf(fn * inv1[j], &s1, &c1);
                    *(__half2*)(base + i0) =
                        __floats2half2_rn((a0*c0 - b0*s0)*sc, (a1*c1 - b1*s1)*sc);
                    *(__half2*)(base + i0 + 32) =
                        __floats2half2_rn((b0*c0 + a0*s0)*sc, (b1*c1 + a1*s1)*sc);
                }
            }
        }
    }
}

// ------------------- fp16 flash attention: no-max softmax, f16x2 exp, ones-mma l ----
// (round-14 proven structure: combined K+V stage, single S[8][4])
#define QS 72
#define KVST (128*QS)
#define ATTN_SMEM ((4*KVST) * 2)   // 73728 B -> 2 CTAs/SM
#define ONESH2 0x3C003C00u

__global__ __launch_bounds__(256, 2) void attn_h() {
    extern __shared__ __align__(16) __half sm[];
    __half* Ks = sm;                // 2 x 128 x 72
    __half* Vs = sm + 2*KVST;       // 2 x 128 x 72

    int tid = threadIdx.x, warp = tid >> 5, lane = tid & 31;
    int r = lane >> 2, cq = lane & 3;
    int bid = blockIdx.x;
    int qt = bid & 15, bh = bid >> 4;
    int b = bh >> 4, head = bh & 15;
    int qrow0 = qt * 128;
    int wq = warp * 16;

    auto loadkv = [&](int kt2, int s) {
        const __half* Kg = g_kh + ((size_t)bh * NN + kt2*128) * HD;
        const __half* Vg = g_vh + ((size_t)bh * NN + kt2*128) * HD;
        #pragma unroll
        for (int i = 0; i < 4; i++) {
            int c = tid + i*256;
            int row = c >> 3, c8 = (c & 7) * 8;
            cpa16(sptr(&Ks[s*KVST + row*QS + c8]), Kg + row*HD + c8);
            cpa16(sptr(&Vs[s*KVST + row*QS + c8]), Vg + row*HD + c8);
        }
    };
    loadkv(0, 0); CP_COMMIT;

    unsigned qa[4][4];
    {
        const __half* Qg = g_qh + ((size_t)bh * NN + qrow0 + wq + r) * HD + cq*2;
        #pragma unroll
        for (int ks = 0; ks < 4; ks++) {
            qa[ks][0] = *(const unsigned*)(Qg + ks*16);
            qa[ks][1] = *(const unsigned*)(Qg + 8*HD + ks*16);
            qa[ks][2] = *(const unsigned*)(Qg + ks*16 + 8);
            qa[ks][3] = *(const unsigned*)(Qg + 8*HD + ks*16 + 8);
        }
    }

    float O[8][4];
    #pragma unroll
    for (int j = 0; j < 8; j++)
        #pragma unroll
        for (int u = 0; u < 4; u++) O[j][u] = 0.f;
    float lf[4] = {0.f, 0.f, 0.f, 0.f};   // row sums via ones-mma

    const unsigned* mrow0 = g_maskbits + ((size_t)b * NN + qrow0 + wq + r) * (NN/32);
    const unsigned* mrow1 = mrow0 + 8 * (NN/32);

    for (int kt2 = 0; kt2 < NN/128; kt2++) {
        CP_WAIT0;
        __syncthreads();
        if (kt2 + 1 < NN/128) loadkv(kt2 + 1, (kt2 + 1) & 1);
        CP_COMMIT;
        int st = (kt2 & 1) * KVST;

        #pragma unroll
        for (int hf = 0; hf < 2; hf++) {
            int sb = st + hf * 64 * QS;
            int kt = kt2*2 + hf;

            float S[8][4];
            #pragma unroll
            for (int j = 0; j < 8; j++)
                #pragma unroll
                for (int u = 0; u < 4; u++) S[j][u] = 0.f;
            #pragma unroll
            for (int ks = 0; ks < 4; ks++) {
                #pragma unroll
                for (int g = 0; g < 4; g++) {
                    unsigned b0, b1, b2, b3;
                    unsigned kd = sptr(&Ks[sb + ((2*g + ((lane>>4)&1))*8 + (lane&7))*QS
                                           + ks*16 + ((lane>>3)&1)*8]);
                    ldsm4(b0, b1, b2, b3, kd);
                    mma16(S[2*g],   qa[ks], b0, b1);
                    mma16(S[2*g+1], qa[ks], b2, b3);
                }
            }

            unsigned mw00 = mrow0[kt*2], mw01 = mrow0[kt*2+1];
            unsigned mw10 = mrow1[kt*2], mw11 = mrow1[kt*2+1];

            // p = mask ? 2^S : 0  (constant 2^-max cancels in O/l)
            #pragma unroll
            for (int ks = 0; ks < 4; ks++) {
                unsigned w0 = (ks < 2) ? mw00 : mw01;   // row_l
                unsigned w1 = (ks < 2) ? mw10 : mw11;   // row_h
                int bA = ((2*ks) & 3)*8 + cq*2;
                int bB = bA + 8;
                float s00 = ((w0 >> bA)     & 1u) ? S[2*ks][0]   : -1e30f;
                float s01 = ((w0 >> (bA+1)) & 1u) ? S[2*ks][1]   : -1e30f;
                float s02 = ((w1 >> bA)     & 1u) ? S[2*ks][2]   : -1e30f;
                float s03 = ((w1 >> (bA+1)) & 1u) ? S[2*ks][3]   : -1e30f;
                float s10 = ((w0 >> bB)     & 1u) ? S[2*ks+1][0] : -1e30f;
                float s11 = ((w0 >> (bB+1)) & 1u) ? S[2*ks+1][1] : -1e30f;
                float s12 = ((w1 >> bB)     & 1u) ? S[2*ks+1][2] : -1e30f;
                float s13 = ((w1 >> (bB+1)) & 1u) ? S[2*ks+1][3] : -1e30f;
                unsigned pk[4];
                pk[0] = ex2h2(cvt2h(s01, s00));
                pk[1] = ex2h2(cvt2h(s03, s02));
                pk[2] = ex2h2(cvt2h(s11, s10));
                pk[3] = ex2h2(cvt2h(s13, s12));
                mma16(lf, pk, ONESH2, ONESH2);   // row sums on tensor pipe
                #pragma unroll
                for (int g = 0; g < 4; g++) {
                    unsigned b0, b1, b2, b3;
                    unsigned vd = sptr(&Vs[sb + (ks*16 + (lane&7) + ((lane>>3)&1)*8)*QS
                                           + (2*g + ((lane>>4)&1))*8]);
                    ldsm4t(b0, b1, b2, b3, vd);
                    mma16(O[2*g],   pk, b0, b1);
                    mma16(O[2*g+1], pk, b2, b3);
                }
            }
        }
    }

    float i0 = (lf[0] > 0.f) ? (1.f / lf[0]) : 0.f;
    float i1 = (lf[2] > 0.f) ? (1.f / lf[2]) : 0.f;
    __half* o0 = g_attnh + ((size_t)b * NN + qrow0 + wq + r) * INNER + head * HD;
    __half* o1 = o0 + 8 * INNER;
    #pragma unroll
    for (int j = 0; j < 8; j++) {
        int col = j*8 + cq*2;
        *(__half2*)&o0[col] = __floats2half2_rn(O[j][0]*i0, O[j][1]*i0);
        *(__half2*)&o1[col] = __floats2half2_rn(O[j][2]*i1, O[j][3]*i1);
    }
}

// ------------------- launch -------------------
extern "C" void kernel_launch(void* const* d_in, const int* in_sizes, int n_in,
                              void* d_out, int out_size) {
    const float* x      = (const float*)d_in[0];
    const int*   mask   = (const int*)  d_in[1];
    const float* gamma  = (const float*)d_in[2];
    const float* beta   = (const float*)d_in[3];
    const float* w_qkv  = (const float*)d_in[4];
    const float* w_out  = (const float*)d_in[5];
    const float* b_out  = (const float*)d_in[6];
    float* out = (float*)d_out;

    static int attr_set = 0;
    if (!attr_set) {
        cudaFuncSetAttribute(attn_h, cudaFuncAttributeMaxDynamicSharedMemorySize, ATTN_SMEM);
        cudaFuncSetAttribute(gemm_h, cudaFuncAttributeMaxDynamicSharedMemorySize, GEMM_SMEM);
        attr_set = 1;
    }

    setup_kernel<<<7169, 256>>>(x, mask, gamma, beta, w_qkv, w_out);
    gemm_h<<<dim3(3*INNER/128, NTOK/128), 256, GEMM_SMEM>>>(3*INNER, 0, nullptr, nullptr);
    attn_h<<<BB*HH*(NN/128), 256, ATTN_SMEM>>>();
    gemm_h<<<dim3(DD/128, NTOK/128), 256, GEMM_SMEM>>>(DD, 1, b_out, out);
}

// round 17
// speedup vs baseline: 1.0798x; 1.0328x over previous
#include <cuda_runtime.h>
#include <cuda_fp16.h>
#include <math.h>

#define BB 2
#define NN 2048
#define DD 1024
#define HH 16
#define HD 64
#define INNER (HH*HD)
#define NTOK (BB*NN)
#define EPS 1e-5f
#define SCQ 0.1803368801111204f   // 0.125 * log2(e)

// ------------------- scratch -------------------
static __device__ __align__(256) __half  g_xnh[NTOK*DD];
static __device__ __align__(256) __half  g_qh[BB*HH*NN*HD];   // rope-applied, pre-scaled by SCQ
static __device__ __align__(256) __half  g_kh[BB*HH*NN*HD];   // rope-applied
static __device__ __align__(256) __half  g_vh[BB*HH*NN*HD];
static __device__ __align__(256) __half  g_attnh[NTOK*INNER];
static __device__ __align__(256) __half  g_wqh[DD*3*INNER];
static __device__ __align__(256) __half  g_woh[INNER*DD];
static __device__ __align__(256) unsigned g_maskbits[BB*NN*(NN/32)];
static __device__ float g_invf[32];

// ------------------- asm helpers -------------------
__device__ __forceinline__ unsigned sptr(const void* p) {
    return (unsigned)__cvta_generic_to_shared(p);
}
__device__ __forceinline__ void cpa16(unsigned s, const void* g) {
    asm volatile("cp.async.cg.shared.global [%0], [%1], 16;\n" :: "r"(s), "l"(g));
}
#define CP_COMMIT asm volatile("cp.async.commit_group;\n" ::: "memory")
#define CP_WAIT1  asm volatile("cp.async.wait_group 1;\n" ::: "memory")
#define CP_WAIT0  asm volatile("cp.async.wait_group 0;\n" ::: "memory")

__device__ __forceinline__ void ldsm4(unsigned& r0, unsigned& r1, unsigned& r2, unsigned& r3, unsigned a) {
    asm volatile("ldmatrix.sync.aligned.m8n8.x4.shared.b16 {%0,%1,%2,%3}, [%4];"
        : "=r"(r0), "=r"(r1), "=r"(r2), "=r"(r3) : "r"(a));
}
__device__ __forceinline__ void ldsm4t(unsigned& r0, unsigned& r1, unsigned& r2, unsigned& r3, unsigned a) {
    asm volatile("ldmatrix.sync.aligned.m8n8.x4.trans.shared.b16 {%0,%1,%2,%3}, [%4];"
        : "=r"(r0), "=r"(r1), "=r"(r2), "=r"(r3) : "r"(a));
}
__device__ __forceinline__ void mma16(float* d, const unsigned* a, unsigned b0, unsigned b1) {
    asm volatile("mma.sync.aligned.m16n8k16.row.col.f32.f16.f16.f32 "
        "{%0,%1,%2,%3}, {%4,%5,%6,%7}, {%8,%9}, {%0,%1,%2,%3};"
        : "+f"(d[0]), "+f"(d[1]), "+f"(d[2]), "+f"(d[3])
        : "r"(a[0]), "r"(a[1]), "r"(a[2]), "r"(a[3]), "r"(b0), "r"(b1));
}
__device__ __forceinline__ unsigned h2pack(float lo, float hi) {
    __half2 h = __floats2half2_rn(lo, hi);
    return *(unsigned*)&h;
}
__device__ __forceinline__ unsigned cvt2h(float hi, float lo) {
    unsigned u; asm("cvt.rn.f16x2.f32 %0, %1, %2;" : "=r"(u) : "f"(hi), "f"(lo)); return u;
}
__device__ __forceinline__ unsigned ex2h2(unsigned x) {
    unsigned y; asm("ex2.approx.f16x2 %0, %1;" : "=r"(y) : "r"(x)); return y;
}

// ------------------- fused setup: weight cvt x2 | layernorm | mask pack | rope table ---
__global__ __launch_bounds__(256) void setup_kernel(const float* __restrict__ x,
                                                    const int* __restrict__ mask,
                                                    const float* __restrict__ gamma,
                                                    const float* __restrict__ beta,
                                                    const float* __restrict__ w_qkv,
                                                    const float* __restrict__ w_out) {
    int bid = blockIdx.x;
    int tid = threadIdx.x;
    if (bid < 2048) {
        const float* src = (bid < 1536) ? w_qkv : w_out;
        __half* dst      = (bid < 1536) ? g_wqh : g_woh;
        int base = (bid < 1536) ? bid : (bid - 1536);
        int i = (base * 256 + tid) * 8;
        float4 v0 = *(const float4*)(src + i);
        float4 v1 = *(const float4*)(src + i + 4);
        uint4 u;
        u.x = h2pack(v0.x, v0.y); u.y = h2pack(v0.z, v0.w);
        u.z = h2pack(v1.x, v1.y); u.w = h2pack(v1.z, v1.w);
        *(uint4*)(dst + i) = u;
    } else if (bid < 6144) {
        int t = bid - 2048;
        const float4* xv = (const float4*)(x + (size_t)t * DD);
        float4 v = xv[tid];
        float s  = v.x + v.y + v.z + v.w;
        float s2 = v.x*v.x + v.y*v.y + v.z*v.z + v.w*v.w;
        #pragma unroll
        for (int off = 16; off; off >>= 1) {
            s  += __shfl_xor_sync(0xffffffffu, s,  off);
            s2 += __shfl_xor_sync(0xffffffffu, s2, off);
        }
        __shared__ float ws[8], ws2[8];
        __shared__ float sh_mean, sh_inv;
        int lane = tid & 31, wid = tid >> 5;
        if (!lane) { ws[wid] = s; ws2[wid] = s2; }
        __syncthreads();
        if (tid == 0) {
            float a = 0.f, c = 0.f;
            #pragma unroll
            for (int i = 0; i < 8; i++) { a += ws[i]; c += ws2[i]; }
            float mean = a * (1.f/(float)DD);
            float var  = c * (1.f/(float)DD) - mean*mean;
            sh_mean = mean;
            sh_inv  = rsqrtf(var + EPS);
        }
        __syncthreads();
        float mean = sh_mean, inv = sh_inv;
        float4 g  = ((const float4*)gamma)[tid];
        float4 be = ((const float4*)beta)[tid];
        uint2 u;
        u.x = h2pack((v.x - mean) * inv * g.x + be.x, (v.y - mean) * inv * g.y + be.y);
        u.y = h2pack((v.z - mean) * inv * g.z + be.z, (v.w - mean) * inv * g.w + be.w);
        *(uint2*)(g_xnh + (size_t)t * DD + tid*4) = u;
    } else if (bid < 7168) {
        int w = (bid - 6144) * 256 + tid;
        const int4* mp = (const int4*)(mask + (size_t)w * 32);
        unsigned bits = 0;
        #pragma unroll
        for (int q = 0; q < 8; q++) {
            int4 m4 = mp[q];
            if (m4.x > 0) bits |= 1u << (q*4 + 0);
            if (m4.y > 0) bits |= 1u << (q*4 + 1);
            if (m4.z > 0) bits |= 1u << (q*4 + 2);
            if (m4.w > 0) bits |= 1u << (q*4 + 3);
        }
        g_maskbits[w] = bits;
    } else {
        if (tid < 32) g_invf[tid] = (float)pow(10000.0, -(double)tid / 32.0);
    }
}

// ------------------- fp16 GEMM: 128x128 tile, K-slab 64, 3-stage, SINGLE sync/slab ---
// mode 0: g_xnh @ g_wqh  -> fused RoPE -> g_qh/g_kh (half) + g_vh, smem-staged epilogue
// mode 1: g_attnh @ g_woh + bias -> out (fp32)
#define GA (128*72)        // A stage: 128 rows x 64 k (stride 72)
#define GB (64*136)        // B stage: 64 k x 128 n (stride 136)
#define GEMM_SMEM ((3*GA + 3*GB) * 2)   // 107520 B

__global__ __launch_bounds__(256, 2) void gemm_h(int Ncols, int mode,
                                                 const float* __restrict__ bias,
                                                 float* __restrict__ out) {
    const __half* A  = mode ? g_attnh : g_xnh;
    const __half* Bm = mode ? g_woh   : g_wqh;
    extern __shared__ __align__(16) __half gsm[];
    __half* As = gsm;
    __half* Bs = gsm + 3*GA;
    int tid = threadIdx.x, warp = tid >> 5, lane = tid & 31;
    int r = lane >> 2, cq = lane & 3;
    int wm = warp & 3, wn = warp >> 2;
    int m0 = blockIdx.y * 128, n0 = blockIdx.x * 128;

    float acc[2][8][4];
    #pragma unroll
    for (int t = 0; t < 2; t++)
        #pragma unroll
        for (int j = 0; j < 8; j++)
            #pragma unroll
            for (int u = 0; u < 4; u++) acc[t][j][u] = 0.f;

    auto loadst = [&](int kb, int s) {
        int k0 = kb * 64;
        __half* as = As + s*GA;
        __half* bs = Bs + s*GB;
        #pragma unroll
        for (int i = 0; i < 4; i++) {
            int c = tid + i*256;
            int row = c >> 3, k8 = (c & 7) * 8;
            cpa16(sptr(&as[row*72 + k8]), A + (size_t)(m0+row)*1024 + k0 + k8);
        }
        #pragma unroll
        for (int i = 0; i < 4; i++) {
            int c = tid + i*256;
            int k = c >> 4, n8 = (c & 15) * 8;
            cpa16(sptr(&bs[k*136 + n8]), Bm + (size_t)(k0+k)*Ncols + n0 + n8);
        }
    };

    loadst(0, 0); CP_COMMIT;
    loadst(1, 1); CP_COMMIT;
    for (int kb = 0; kb < 16; kb++) {
        CP_WAIT1;                 // slab kb's copies complete
        __syncthreads();          // also orders prior compute-reads before new writes
        if (kb + 2 < 16) loadst(kb + 2, (kb + 2) % 3);
        CP_COMMIT;
        int s = kb % 3;
        __half* as = As + s*GA;
        __half* bs = Bs + s*GB;
        #pragma unroll
        for (int ks = 0; ks < 4; ks++) {
            unsigned a[2][4];
            #pragma unroll
            for (int t = 0; t < 2; t++) {
                unsigned ad = sptr(&as[(wm*32 + t*16 + (lane&7) + ((lane>>3)&1)*8)*72
                                       + ks*16 + ((lane>>4)&1)*8]);
                ldsm4(a[t][0], a[t][1], a[t][2], a[t][3], ad);
            }
            #pragma unroll
            for (int g = 0; g < 4; g++) {
                unsigned b0, b1, b2, b3;
                unsigned bd = sptr(&bs[(ks*16 + (lane&7) + ((lane>>3)&1)*8)*136
                                       + wn*64 + g*16 + ((lane>>4)&1)*8]);
                ldsm4t(b0, b1, b2, b3, bd);
                mma16(acc[0][2*g],   a[0], b0, b1);
                mma16(acc[1][2*g],   a[1], b0, b1);
                mma16(acc[0][2*g+1], a[0], b2, b3);
                mma16(acc[1][2*g+1], a[1], b2, b3);
            }
        }
        // no trailing sync: next iteration's top barrier provides the ordering
    }

    if (mode == 1) {
        #pragma unroll
        for (int t = 0; t < 2; t++) {
            int row_l = m0 + wm*32 + t*16 + r;
            int row_h = row_l + 8;
            #pragma unroll
            for (int j = 0; j < 8; j++) {
                int col0 = n0 + wn*64 + j*8 + cq*2;
                float2 bv = *(const float2*)&bias[col0];
                *(float2*)&out[(size_t)row_l*1024 + col0] =
                    make_float2(acc[t][j][0] + bv.x, acc[t][j][1] + bv.y);
                *(float2*)&out[(size_t)row_h*1024 + col0] =
                    make_float2(acc[t][j][2] + bv.x, acc[t][j][3] + bv.y);
            }
        }
        return;
    }

    // ---- mode 0 epilogue: stage through smem, then coalesced stores ----
    __syncthreads();              // all warps done with pipeline stages
    __half* stage = gsm;          // 128 x 136 halves (34.8 KB, fits in pipeline smem)
    int which = n0 >> 10;         // 0=q 1=k 2=v

    if (which == 2) {
        #pragma unroll
        for (int t = 0; t < 2; t++)
            #pragma unroll
            for (int j = 0; j < 8; j++) {
                int col = wn*64 + j*8 + cq*2;
                int row0 = wm*32 + t*16 + r;
                *(__half2*)&stage[row0*136 + col] =
                    __floats2half2_rn(acc[t][j][0], acc[t][j][1]);
                *(__half2*)&stage[(row0+8)*136 + col] =
                    __floats2half2_rn(acc[t][j][2], acc[t][j][3]);
            }
    } else {
        // fused RoPE: head-local pair (i, i+32) = fragments (j, j+4), same thread
        float sc = which ? 1.0f : SCQ;
        #pragma unroll
        for (int t = 0; t < 2; t++)
            #pragma unroll
            for (int u = 0; u < 2; u++) {
                int srow = wm*32 + t*16 + r + u*8;
                int n = (m0 + srow) & 2047;
                float fn = (float)n;
                #pragma unroll
                for (int j = 0; j < 4; j++) {
                    int i0 = j*8 + cq*2;
                    float a0 = acc[t][j][2*u],   a1 = acc[t][j][2*u+1];
                    float b0 = acc[t][j+4][2*u], b1 = acc[t][j+4][2*u+1];
                    float s0, c0, s1, c1;
                    sincosf(fn * g_invf[i0],     &s0, &c0);
                    sincosf(fn * g_invf[i0 + 1], &s1, &c1);
                    *(__half2*)&stage[srow*136 + wn*64 + i0] =
                        __floats2half2_rn((a0*c0 - b0*s0)*sc, (a1*c1 - b1*s1)*sc);
                    *(__half2*)&stage[srow*136 + wn*64 + i0 + 32] =
                        __floats2half2_rn((b0*c0 + a0*s0)*sc, (b1*c1 + a1*s1)*sc);
                }
            }
    }
    __syncthreads();

    // coalesced copy-out: 256 row-segments (128 rows x 2 heads), 8 lanes per segment
    __half* dstbase = (which == 0) ? g_qh : (which == 1) ? g_kh : g_vh;
    int h0 = (n0 & 1023) >> 6;
    int off = tid & 7;            // 16B unit within a 128B segment
    #pragma unroll
    for (int p = 0; p < 8; p++) {
        int rseg = (tid >> 3) + p*32;   // 0..255
        int row = rseg >> 1, seg = rseg & 1;
        int mrow = m0 + row;
        int b = mrow >> 11, n = mrow & 2047;
        __half* dst = dstbase + (((size_t)(b*HH + h0 + seg)) * NN + n) * HD;
        *(uint4*)(dst + off*8) = *(uint4*)&stage[row*136 + seg*64 + off*8];
    }
}

// ------------------- fp16 flash attention: no-max softmax, f16x2 exp, ones-mma l ----
#define QS 72
#define KVST (128*QS)
#define ATTN_SMEM ((4*KVST) * 2)   // 73728 B -> 2 CTAs/SM
#define ONESH2 0x3C003C00u

__global__ __launch_bounds__(256, 2) void attn_h() {
    extern __shared__ __align__(16) __half sm[];
    __half* Ks = sm;                // 2 x 128 x 72
    __half* Vs = sm + 2*KVST;       // 2 x 128 x 72

    int tid = threadIdx.x, warp = tid >> 5, lane = tid & 31;
    int r = lane >> 2, cq = lane & 3;
    int bid = blockIdx.x;
    int qt = bid & 15, bh = bid >> 4;
    int b = bh >> 4, head = bh & 15;
    int qrow0 = qt * 128;
    int wq = warp * 16;

    auto loadkv = [&](int kt2, int s) {
        const __half* Kg = g_kh + ((size_t)bh * NN + kt2*128) * HD;
        const __half* Vg = g_vh + ((size_t)bh * NN + kt2*128) * HD;
        #pragma unroll
        for (int i = 0; i < 4; i++) {
            int c = tid + i*256;
            int row = c >> 3, c8 = (c & 7) * 8;
            cpa16(sptr(&Ks[s*KVST + row*QS + c8]), Kg + row*HD + c8);
            cpa16(sptr(&Vs[s*KVST + row*QS + c8]), Vg + row*HD + c8);
        }
    };
    loadkv(0, 0); CP_COMMIT;

    unsigned qa[4][4];
    {
        const __half* Qg = g_qh + ((size_t)bh * NN + qrow0 + wq + r) * HD + cq*2;
        #pragma unroll
        for (int ks = 0; ks < 4; ks++) {
            qa[ks][0] = *(const unsigned*)(Qg + ks*16);
            qa[ks][1] = *(const unsigned*)(Qg + 8*HD + ks*16);
            qa[ks][2] = *(const unsigned*)(Qg + ks*16 + 8);
            qa[ks][3] = *(const unsigned*)(Qg + 8*HD + ks*16 + 8);
        }
    }

    float O[8][4];
    #pragma unroll
    for (int j = 0; j < 8; j++)
        #pragma unroll
        for (int u = 0; u < 4; u++) O[j][u] = 0.f;
    float lf[4] = {0.f, 0.f, 0.f, 0.f};   // row sums via ones-mma

    const unsigned* mrow0 = g_maskbits + ((size_t)b * NN + qrow0 + wq + r) * (NN/32);
    const unsigned* mrow1 = mrow0 + 8 * (NN/32);

    for (int kt2 = 0; kt2 < NN/128; kt2++) {
        CP_WAIT0;
        __syncthreads();
        if (kt2 + 1 < NN/128) loadkv(kt2 + 1, (kt2 + 1) & 1);
        CP_COMMIT;
        int st = (kt2 & 1) * KVST;

        #pragma unroll
        for (int hf = 0; hf < 2; hf++) {
            int sb = st + hf * 64 * QS;
            int kt = kt2*2 + hf;

            float S[8][4];
            #pragma unroll
            for (int j = 0; j < 8; j++)
                #pragma unroll
                for (int u = 0; u < 4; u++) S[j][u] = 0.f;
            #pragma unroll
            for (int ks = 0; ks < 4; ks++) {
                #pragma unroll
                for (int g = 0; g < 4; g++) {
                    unsigned b0, b1, b2, b3;
                    unsigned kd = sptr(&Ks[sb + ((2*g + ((lane>>4)&1))*8 + (lane&7))*QS
                                           + ks*16 + ((lane>>3)&1)*8]);
                    ldsm4(b0, b1, b2, b3, kd);
                    mma16(S[2*g],   qa[ks], b0, b1);
                    mma16(S[2*g+1], qa[ks], b2, b3);
                }
            }

            unsigned mw00 = mrow0[kt*2], mw01 = mrow0[kt*2+1];
            unsigned mw10 = mrow1[kt*2], mw11 = mrow1[kt*2+1];

            // p = mask ? 2^S : 0  (constant 2^-max cancels in O/l)
            #pragma unroll
            for (int ks = 0; ks < 4; ks++) {
                unsigned w0 = (ks < 2) ? mw00 : mw01;   // row_l
                unsigned w1 = (ks < 2) ? mw10 : mw11;   // row_h
                int bA = ((2*ks) & 3)*8 + cq*2;
                int bB = bA + 8;
                float s00 = ((w0 >> bA)     & 1u) ? S[2*ks][0]   : -1e30f;
                float s01 = ((w0 >> (bA+1)) & 1u) ? S[2*ks][1]   : -1e30f;
                float s02 = ((w1 >> bA)     & 1u) ? S[2*ks][2]   : -1e30f;
                float s03 = ((w1 >> (bA+1)) & 1u) ? S[2*ks][3]   : -1e30f;
                float s10 = ((w0 >> bB)     & 1u) ? S[2*ks+1][0] : -1e30f;
                float s11 = ((w0 >> (bB+1)) & 1u) ? S[2*ks+1][1] : -1e30f;
                float s12 = ((w1 >> bB)     & 1u) ? S[2*ks+1][2] : -1e30f;
                float s13 = ((w1 >> (bB+1)) & 1u) ? S[2*ks+1][3] : -1e30f;
                unsigned pk[4];
                pk[0] = ex2h2(cvt2h(s01, s00));
                pk[1] = ex2h2(cvt2h(s03, s02));
                pk[2] = ex2h2(cvt2h(s11, s10));
                pk[3] = ex2h2(cvt2h(s13, s12));
                mma16(lf, pk, ONESH2, ONESH2);   // row sums on tensor pipe
                #pragma unroll
                for (int g = 0; g < 4; g++) {
                    unsigned b0, b1, b2, b3;
                    unsigned vd = sptr(&Vs[sb + (ks*16 + (lane&7) + ((lane>>3)&1)*8)*QS
                                           + (2*g + ((lane>>4)&1))*8]);
                    ldsm4t(b0, b1, b2, b3, vd);
                    mma16(O[2*g],   pk, b0, b1);
                    mma16(O[2*g+1], pk, b2, b3);
                }
            }
        }
    }

    float i0 = (lf[0] > 0.f) ? (1.f / lf[0]) : 0.f;
    float i1 = (lf[2] > 0.f) ? (1.f / lf[2]) : 0.f;
    __half* o0 = g_attnh + ((size_t)b * NN + qrow0 + wq + r) * INNER + head * HD;
    __half* o1 = o0 + 8 * INNER;
    #pragma unroll
    for (int j = 0; j < 8; j++) {
        int col = j*8 + cq*2;
        *(__half2*)&o0[col] = __floats2half2_rn(O[j][0]*i0, O[j][1]*i0);
        *(__half2*)&o1[col] = __floats2half2_rn(O[j][2]*i1, O[j][3]*i1);
    }
}

// ------------------- launch -------------------
extern "C" void kernel_launch(void* const* d_in, const int* in_sizes, int n_in,
                              void* d_out, int out_size) {
    const float* x      = (const float*)d_in[0];
    const int*   mask   = (const int*)  d_in[1];
    const float* gamma  = (const float*)d_in[2];
    const float* beta   = (const float*)d_in[3];
    const float* w_qkv  = (const float*)d_in[4];
    const float* w_out  = (const float*)d_in[5];
    const float* b_out  = (const float*)d_in[6];
    float* out = (float*)d_out;

    static int attr_set = 0;
    if (!attr_set) {
        cudaFuncSetAttribute(attn_h, cudaFuncAttributeMaxDynamicSharedMemorySize, ATTN_SMEM);
        cudaFuncSetAttribute(gemm_h, cudaFuncAttributeMaxDynamicSharedMemorySize, GEMM_SMEM);
        attr_set = 1;
    }

    setup_kernel<<<7169, 256>>>(x, mask, gamma, beta, w_qkv, w_out);
    gemm_h<<<dim3(3*INNER/128, NTOK/128), 256, GEMM_SMEM>>>(3*INNER, 0, nullptr, nullptr);
    attn_h<<<BB*HH*(NN/128), 256, ATTN_SMEM>>>();
    gemm_h<<<dim3(DD/128, NTOK/128), 256, GEMM_SMEM>>>(DD, 1, b_out, out);
}